// round 11
// baseline (speedup 1.0000x reference)
#include <cuda_runtime.h>
#include <math.h>

#define NSTEPS 130
#define NLUT   27
#define ROWS   32
#define UROWS  132          // 130 data rows + 2 padding rows for tail prefetch

// srcA[l] / srcB[l]: flat-state index feeding mux selects A / B of LUT-lane l.
// Lanes 27..31 are constant-carrier lanes (self-wired).
__device__ __constant__ int c_srcA[32] = {
    1, 3, 3,   7, 0, 0,   4, 6, 6,   19, 12, 12,  16, 9, 9,
    13, 15, 15, 10, 18, 18, 22, 6, 6, 25, 15, 15,
    27, 28, 29, 30, 31};
__device__ __constant__ int c_srcB[32] = {
    17, 17, 1,  5, 5, 7,   11, 11, 4, 8, 8, 19,   28, 28, 16,
    2, 2, 13,   27, 27, 10, 23, 23, 22, 26, 26, 25,
    27, 28, 29, 30, 31};

#define BAR_ARRIVE(b) asm volatile("bar.arrive %0, 64;" :: "r"(b) : "memory")
#define BAR_WAIT(b)   asm volatile("bar.sync %0, 64;"   :: "r"(b) : "memory")

__global__ void one_layer_net_kernel(const float* __restrict__ x,
                                     const float* __restrict__ weights,
                                     const float4* __restrict__ noise4,
                                     float* __restrict__ out) {
    extern __shared__ float4 s_uvrs[];   // [132][32] quadruples

    const int tid  = threadIdx.x;
    const int wrp  = tid >> 5;
    const int lane = tid & 31;

    if (wrp == 4) return;   // SMSP0 reserved for the consumer warp

    if (wrp > 0) {
        // --------------- PRODUCER WARPS (1,2,3,5,6,7) ----------------------
        // Row map (graded to the consumer's arrival schedule):
        //   w1: rows 0..3 (+pads 130,131)  -> bar1
        //   w2: rows 4..13   (10)          -> bar2
        //   w3: rows 14..29  (16)          -> bar3
        //   w5: rows 30..55  (26)          -> bar4
        //   w6: rows 56..87  (32)          -> bar5
        //   w7: rows 88..129 (42)          -> bar6
        const bool act = (lane < NLUT);
        const int  nl  = act ? lane : 0;

        float4 wb = make_float4(0.f, 0.f, 0.f, 0.f);

        if (wrp == 1) {
            float4 nb[4];
#pragma unroll
            for (int i = 0; i < 4; ++i) nb[i] = noise4[i * NLUT + nl];

            // Padding rows (zeros); visibility to consumer ordered by bar1.
            s_uvrs[130 * ROWS + lane] = make_float4(0.f, 0.f, 0.f, 0.f);
            s_uvrs[131 * ROWS + lane] = make_float4(0.f, 0.f, 0.f, 0.f);

            if (act) wb = reinterpret_cast<const float4*>(weights)[lane];
            const float c0 = fabsf(1.0f - fabsf(wb.x)) * 0.125f;
            const float c1 = fabsf(1.0f - fabsf(wb.y)) * 0.125f;
            const float c2 = fabsf(1.0f - fabsf(wb.z)) * 0.125f;
            const float c3 = fabsf(1.0f - fabsf(wb.w)) * 0.125f;
            const float xv = (lane == 27) ? x[0] : ((lane == 28) ? x[1] : 0.0f);

#pragma unroll
            for (int i = 0; i < 4; ++i) {
                const float4 n = nb[i];
                const float w0 = fmaf(c0, n.x, wb.x);
                const float w1 = fmaf(c1, n.y, wb.y);
                const float w2 = fmaf(c2, n.z, wb.z);
                const float w3 = fmaf(c3, n.w, wb.w);
                const float d01 = w1 - w0, d23 = w3 - w2;
                const float p01 = w0 + w1, p23 = w2 + w3;
                float4 q;
                q.x = act ? 0.25f * (d23 - d01) : 0.f;
                q.y = act ? 0.25f * (p23 - p01) : 0.f;
                q.z = act ? 0.25f * (d01 + d23) : 0.f;
                q.w = act ? 0.25f * (p01 + p23) : xv;
                s_uvrs[i * ROWS + lane] = q;
            }
            int b = 1;
            BAR_ARRIVE(b);
            return;
        }

        int s0, len, bar;
        switch (wrp) {
            case 2:  s0 = 4;  len = 10; bar = 2; break;
            case 3:  s0 = 14; len = 16; bar = 3; break;
            case 5:  s0 = 30; len = 26; bar = 4; break;
            case 6:  s0 = 56; len = 32; bar = 5; break;
            default: s0 = 88; len = 42; bar = 6; break;   // wrp == 7
        }

        if (act) wb = reinterpret_cast<const float4*>(weights)[lane];
        const float c0 = fabsf(1.0f - fabsf(wb.x)) * 0.125f;
        const float c1 = fabsf(1.0f - fabsf(wb.y)) * 0.125f;
        const float c2 = fabsf(1.0f - fabsf(wb.z)) * 0.125f;
        const float c3 = fabsf(1.0f - fabsf(wb.w)) * 0.125f;
        const float xv = (lane == 27) ? x[0] : ((lane == 28) ? x[1] : 0.0f);

        // Chunked processing: 16 front-batched LDGs (64 regs) per chunk.
#pragma unroll 1
        for (int base = 0; base < len; base += 16) {
            float4 nb[16];
#pragma unroll
            for (int i = 0; i < 16; ++i) {
                const int rr = (base + i < len) ? (base + i) : (len - 1);
                nb[i] = noise4[(s0 + rr) * NLUT + nl];
            }
#pragma unroll
            for (int i = 0; i < 16; ++i) {
                if (base + i >= len) break;
                const float4 n = nb[i];
                const float w0 = fmaf(c0, n.x, wb.x);
                const float w1 = fmaf(c1, n.y, wb.y);
                const float w2 = fmaf(c2, n.z, wb.z);
                const float w3 = fmaf(c3, n.w, wb.w);
                const float d01 = w1 - w0, d23 = w3 - w2;
                const float p01 = w0 + w1, p23 = w2 + w3;
                float4 q;
                q.x = act ? 0.25f * (d23 - d01) : 0.f;
                q.y = act ? 0.25f * (p23 - p01) : 0.f;
                q.z = act ? 0.25f * (d01 + d23) : 0.f;
                q.w = act ? 0.25f * (p01 + p23) : xv;
                s_uvrs[(s0 + base + i) * ROWS + lane] = q;
            }
        }
        BAR_ARRIVE(bar);
        return;
    }

    // ----------------------- CONSUMER WARP (0) -----------------------------
    const int sa = c_srcA[lane];
    const int sb = c_srcB[lane];
    const int aa = c_srcA[sa], ba = c_srcB[sa];
    const int ab = c_srcA[sb], bb = c_srcB[sb];

    float state = (lane < NLUT) ? -1.0f
                : (lane == 27) ? x[0]
                : (lane == 28) ? x[1] : 0.0f;

    int b = 1;
    BAR_WAIT(b);   // rows 0..3 (+pads) ready

    const float4* pAp = s_uvrs + sa;
    const float4* pBp = s_uvrs + sb;
    const float4* pFp = s_uvrs + ROWS + lane;
    float4 cA = pAp[0];
    float4 cB = pBp[0];
    float4 cF = pFp[0];
    pAp += 2 * ROWS; pBp += 2 * ROWS; pFp += 2 * ROWS;

#define SCAN_ITER()                                                          \
    do {                                                                     \
        const float4 pA = pAp[0];                                            \
        const float4 pB = pBp[0];                                            \
        const float4 pF = pFp[0];                                            \
        pAp += 2 * ROWS; pBp += 2 * ROWS; pFp += 2 * ROWS;                   \
        const float aAv = __shfl_sync(0xFFFFFFFFu, state, aa);               \
        const float bAv = __shfl_sync(0xFFFFFFFFu, state, ba);               \
        const float aBv = __shfl_sync(0xFFFFFFFFu, state, ab);               \
        const float bBv = __shfl_sync(0xFFFFFFFFu, state, bb);               \
        const float iA = fmaf(bAv, fmaf(aAv, cA.x, cA.y),                    \
                              fmaf(aAv, cA.z, cA.w));                        \
        const float iB = fmaf(bBv, fmaf(aBv, cB.x, cB.y),                    \
                              fmaf(aBv, cB.z, cB.w));                        \
        state = fmaf(iB, fmaf(iA, cF.x, cF.y), fmaf(iA, cF.z, cF.w));        \
        cA = pA; cB = pB; cF = pF;                                           \
    } while (0)

    // iter k consumes rows 2k,2k+1 and prefetches rows 2k+2,2k+3
    // (needs rows <= 2k+3):
    //   k=0      <=3    (bar1, passed)      k=1..5   <=13   (bar2)
    //   k=6..13  <=29   (bar3)              k=14..26 <=55   (bar4)
    //   k=27..42 <=87   (bar5)              k=43..64 <=131  (bar6 + pads)
    SCAN_ITER();
    b = 2; BAR_WAIT(b);
#pragma unroll
    for (int i = 0; i < 5; ++i) SCAN_ITER();
    b = 3; BAR_WAIT(b);
#pragma unroll
    for (int i = 0; i < 8; ++i) SCAN_ITER();
    b = 4; BAR_WAIT(b);
#pragma unroll
    for (int i = 0; i < 13; ++i) SCAN_ITER();
    b = 5; BAR_WAIT(b);
#pragma unroll
    for (int i = 0; i < 16; ++i) SCAN_ITER();
    b = 6; BAR_WAIT(b);
#pragma unroll
    for (int i = 0; i < 22; ++i) SCAN_ITER();

    // Outputs: final[0,1] -> flat 1, final[1,2] -> flat 5, final[7,2] -> flat 23.
    if (lane == 1)  out[0] = state;
    if (lane == 5)  out[1] = state;
    if (lane == 23) out[2] = state;
}

extern "C" void kernel_launch(void* const* d_in, const int* in_sizes, int n_in,
                              void* d_out, int out_size) {
    (void)in_sizes; (void)n_in; (void)out_size;
    const float*  x  = (const float*)d_in[0];      // [2]
    const float*  w  = (const float*)d_in[1];      // [9,3,4]
    const float4* nz = (const float4*)d_in[2];     // [130,9,3,4] as float4
    float* out = (float*)d_out;                    // [3]

    const size_t smem = (size_t)UROWS * ROWS * sizeof(float4);   // 67584 B
    cudaFuncSetAttribute(one_layer_net_kernel,
                         cudaFuncAttributeMaxDynamicSharedMemorySize, (int)smem);
    one_layer_net_kernel<<<1, 256, smem>>>(x, w, nz, out);
}

// round 12
// speedup vs baseline: 1.2294x; 1.2294x over previous
#include <cuda_runtime.h>
#include <math.h>

#define NSTEPS 130
#define NLUT   27
#define ROWS   32
#define UROWS  132          // 130 data rows + 2 padding rows for tail prefetch

// srcA[l] / srcB[l]: flat-state index feeding mux selects A / B of LUT-lane l.
// Lanes 27..31 are constant-carrier lanes (self-wired).
__device__ __constant__ int c_srcA[32] = {
    1, 3, 3,   7, 0, 0,   4, 6, 6,   19, 12, 12,  16, 9, 9,
    13, 15, 15, 10, 18, 18, 22, 6, 6, 25, 15, 15,
    27, 28, 29, 30, 31};
__device__ __constant__ int c_srcB[32] = {
    17, 17, 1,  5, 5, 7,   11, 11, 4, 8, 8, 19,   28, 28, 16,
    2, 2, 13,   27, 27, 10, 23, 23, 22, 26, 26, 25,
    27, 28, 29, 30, 31};

#define BAR_ARRIVE(b, n) asm volatile("bar.arrive %0, %1;" :: "r"(b), "n"(n) : "memory")
#define BAR_WAIT(b, n)   asm volatile("bar.sync %0, %1;"   :: "r"(b), "n"(n) : "memory")

__global__ void one_layer_net_kernel(const float* __restrict__ x,
                                     const float* __restrict__ weights,
                                     const float4* __restrict__ noise4,
                                     float* __restrict__ out) {
    extern __shared__ float4 s_uvrs[];   // [132][32] quadruples

    const int tid  = threadIdx.x;
    const int wrp  = tid >> 5;
    const int lane = tid & 31;

    if (wrp > 0) {
        // ------------------- PRODUCER WARPS (1..7) — identical to R7 -------
        const bool act = (lane < NLUT);
        const int  nl  = act ? lane : 0;

        // warp1 -> rows 0..5, warps 2..7 -> 20 rows each (6..125),
        // warp1 pass 2 -> rows 126..129 + 2 pads.
        const int s0 = (wrp == 1) ? 0 : 6 + 20 * (wrp - 2);
        const int nrows = (wrp == 1) ? 6 : 20;

        // Front-batch noise loads (max MLP) BEFORE the weights load.
        float4 nbuf[20];
#pragma unroll
        for (int i = 0; i < 20; ++i)
            if (i < nrows) nbuf[i] = noise4[(s0 + i) * NLUT + nl];

        float4 wb = make_float4(0.f, 0.f, 0.f, 0.f);
        if (act) wb = reinterpret_cast<const float4*>(weights)[lane];
        const float c0 = fabsf(1.0f - fabsf(wb.x)) * 0.125f;
        const float c1 = fabsf(1.0f - fabsf(wb.y)) * 0.125f;
        const float c2 = fabsf(1.0f - fabsf(wb.z)) * 0.125f;
        const float c3 = fabsf(1.0f - fabsf(wb.w)) * 0.125f;
        const float xv = (lane == 27) ? x[0] : ((lane == 28) ? x[1] : 0.0f);

#pragma unroll
        for (int i = 0; i < 20; ++i) {
            if (i >= nrows) break;
            const float4 n = nbuf[i];
            const float w0 = fmaf(c0, n.x, wb.x);
            const float w1 = fmaf(c1, n.y, wb.y);
            const float w2 = fmaf(c2, n.z, wb.z);
            const float w3 = fmaf(c3, n.w, wb.w);
            const float d01 = w1 - w0, d23 = w3 - w2;
            const float p01 = w0 + w1, p23 = w2 + w3;
            float4 q;
            q.x = act ? 0.25f * (d23 - d01) : 0.f;
            q.y = act ? 0.25f * (p23 - p01) : 0.f;
            q.z = act ? 0.25f * (d01 + d23) : 0.f;
            q.w = act ? 0.25f * (p01 + p23) : xv;
            s_uvrs[(s0 + i) * ROWS + lane] = q;
        }
        // warps 1..4: individual 64-thread barriers; warps 5..7 share bar 5.
        if (wrp <= 4) { int bw = wrp; BAR_ARRIVE(bw, 64); }
        else          { int b5 = 5;  BAR_ARRIVE(b5, 128); }

        if (wrp == 1) {
            // Second pass: rows 126..129 real, 130..131 zero padding.
            float4 nb2[4];
#pragma unroll
            for (int i = 0; i < 4; ++i)
                nb2[i] = noise4[(126 + i) * NLUT + nl];
#pragma unroll
            for (int i = 0; i < 4; ++i) {
                const float4 n = nb2[i];
                const float w0 = fmaf(c0, n.x, wb.x);
                const float w1 = fmaf(c1, n.y, wb.y);
                const float w2 = fmaf(c2, n.z, wb.z);
                const float w3 = fmaf(c3, n.w, wb.w);
                const float d01 = w1 - w0, d23 = w3 - w2;
                const float p01 = w0 + w1, p23 = w2 + w3;
                float4 q;
                q.x = act ? 0.25f * (d23 - d01) : 0.f;
                q.y = act ? 0.25f * (p23 - p01) : 0.f;
                q.z = act ? 0.25f * (d01 + d23) : 0.f;
                q.w = act ? 0.25f * (p01 + p23) : xv;
                s_uvrs[(126 + i) * ROWS + lane] = q;
            }
            s_uvrs[130 * ROWS + lane] = make_float4(0.f, 0.f, 0.f, 0.f);
            s_uvrs[131 * ROWS + lane] = make_float4(0.f, 0.f, 0.f, 0.f);
            int b8 = 8;
            BAR_ARRIVE(b8, 64);
        }
        return;
    }

    // ----------------------- CONSUMER WARP (0) -----------------------------
    const int sa = c_srcA[lane];
    const int sb = c_srcB[lane];
    const int aa = c_srcA[sa], ba = c_srcB[sa];
    const int ab = c_srcA[sb], bb = c_srcB[sb];

    float state = (lane < NLUT) ? -1.0f
                : (lane == 27) ? x[0]
                : (lane == 28) ? x[1] : 0.0f;

    // Hoist iter-0's shfls ABOVE the first barrier: they depend only on the
    // initial state, not on SMEM contents.
    float aAv = __shfl_sync(0xFFFFFFFFu, state, aa);
    float bAv = __shfl_sync(0xFFFFFFFFu, state, ba);
    float aBv = __shfl_sync(0xFFFFFFFFu, state, ab);
    float bBv = __shfl_sync(0xFFFFFFFFu, state, bb);

    int b = 1;
    BAR_WAIT(b, 64);   // rows 0..5 ready

    const float4* pAp = s_uvrs + sa;
    const float4* pBp = s_uvrs + sb;
    const float4* pFp = s_uvrs + ROWS + lane;
    float4 cA = pAp[0];
    float4 cB = pBp[0];
    float4 cF = pFp[0];
    pAp += 2 * ROWS; pBp += 2 * ROWS; pFp += 2 * ROWS;

    // Finish iter 0 (shfls already done above).
    {
        const float4 pA = pAp[0];
        const float4 pB = pBp[0];
        const float4 pF = pFp[0];
        pAp += 2 * ROWS; pBp += 2 * ROWS; pFp += 2 * ROWS;
        const float iA = fmaf(bAv, fmaf(aAv, cA.x, cA.y), fmaf(aAv, cA.z, cA.w));
        const float iB = fmaf(bBv, fmaf(aBv, cB.x, cB.y), fmaf(aBv, cB.z, cB.w));
        state = fmaf(iB, fmaf(iA, cF.x, cF.y), fmaf(iA, cF.z, cF.w));
        cA = pA; cB = pB; cF = pF;
    }

// SHFLs first (loop-carried critical path), LDS prefetches after — the
// prefetched quadruples are consumed only in the NEXT iteration, so the
// ~12cyc MIO-issue delay moves off the chain.
#define SCAN_ITER()                                                          \
    do {                                                                     \
        aAv = __shfl_sync(0xFFFFFFFFu, state, aa);                           \
        bAv = __shfl_sync(0xFFFFFFFFu, state, ba);                           \
        aBv = __shfl_sync(0xFFFFFFFFu, state, ab);                           \
        bBv = __shfl_sync(0xFFFFFFFFu, state, bb);                           \
        const float4 pA = pAp[0];                                            \
        const float4 pB = pBp[0];                                            \
        const float4 pF = pFp[0];                                            \
        pAp += 2 * ROWS; pBp += 2 * ROWS; pFp += 2 * ROWS;                   \
        const float iA = fmaf(bAv, fmaf(aAv, cA.x, cA.y),                    \
                              fmaf(aAv, cA.z, cA.w));                        \
        const float iB = fmaf(bBv, fmaf(aBv, cB.x, cB.y),                    \
                              fmaf(aBv, cB.z, cB.w));                        \
        state = fmaf(iB, fmaf(iA, cF.x, cF.y), fmaf(iA, cF.z, cF.w));        \
        cA = pA; cB = pB; cF = pF;                                           \
    } while (0)

    // iter k consumes rows 2k,2k+1 and prefetches rows 2k+2,2k+3:
    //   k=0      rows <=3    (bar 1, passed; iter 0 done above)
    //   k=1..10  rows <=23   (bar 2) ... 20-row blocks per bar ...
    //   k=51..60 rows <=123  (bar 7 == shared bar 5 group)
    //   k=61..64 rows <=131  (bar 8)
    b = 2; BAR_WAIT(b, 64);
#pragma unroll
    for (int i = 0; i < 10; ++i) SCAN_ITER();
    b = 3; BAR_WAIT(b, 64);
#pragma unroll
    for (int i = 0; i < 10; ++i) SCAN_ITER();
    b = 4; BAR_WAIT(b, 64);
#pragma unroll
    for (int i = 0; i < 10; ++i) SCAN_ITER();
    b = 5; BAR_WAIT(b, 128);
#pragma unroll
    for (int i = 0; i < 30; ++i) SCAN_ITER();
    b = 8; BAR_WAIT(b, 64);
    SCAN_ITER();
    SCAN_ITER();
    SCAN_ITER();
    SCAN_ITER();

    // Outputs: final[0,1] -> flat 1, final[1,2] -> flat 5, final[7,2] -> flat 23.
    if (lane == 1)  out[0] = state;
    if (lane == 5)  out[1] = state;
    if (lane == 23) out[2] = state;
}

extern "C" void kernel_launch(void* const* d_in, const int* in_sizes, int n_in,
                              void* d_out, int out_size) {
    (void)in_sizes; (void)n_in; (void)out_size;
    const float*  x  = (const float*)d_in[0];      // [2]
    const float*  w  = (const float*)d_in[1];      // [9,3,4]
    const float4* nz = (const float4*)d_in[2];     // [130,9,3,4] as float4
    float* out = (float*)d_out;                    // [3]

    const size_t smem = (size_t)UROWS * ROWS * sizeof(float4);   // 67584 B
    cudaFuncSetAttribute(one_layer_net_kernel,
                         cudaFuncAttributeMaxDynamicSharedMemorySize, (int)smem);
    one_layer_net_kernel<<<1, 256, smem>>>(x, w, nz, out);
}

// round 13
// speedup vs baseline: 1.2657x; 1.0295x over previous
#include <cuda_runtime.h>
#include <math.h>

#define NSTEPS 130
#define NLUT   27
#define ROWS   32
#define UROWS  132          // 130 data rows + 2 padding rows for tail prefetch

// srcA[l] / srcB[l]: flat-state index feeding mux selects A / B of LUT-lane l.
// Lanes 27..31 are constant-carrier lanes (self-wired).
__device__ __constant__ int c_srcA[32] = {
    1, 3, 3,   7, 0, 0,   4, 6, 6,   19, 12, 12,  16, 9, 9,
    13, 15, 15, 10, 18, 18, 22, 6, 6, 25, 15, 15,
    27, 28, 29, 30, 31};
__device__ __constant__ int c_srcB[32] = {
    17, 17, 1,  5, 5, 7,   11, 11, 4, 8, 8, 19,   28, 28, 16,
    2, 2, 13,   27, 27, 10, 23, 23, 22, 26, 26, 25,
    27, 28, 29, 30, 31};

#define BAR_ARRIVE(b, n) asm volatile("bar.arrive %0, %1;" :: "r"(b), "n"(n) : "memory")
#define BAR_WAIT(b, n)   asm volatile("bar.sync %0, %1;"   :: "r"(b), "n"(n) : "memory")

__global__ void one_layer_net_kernel(const float* __restrict__ x,
                                     const float* __restrict__ weights,
                                     const float4* __restrict__ noise4,
                                     float* __restrict__ out) {
    extern __shared__ float4 s_uvrs[];   // [132][32] quadruples

    const int tid  = threadIdx.x;
    const int wrp  = tid >> 5;
    const int lane = tid & 31;

    if (wrp > 0) {
        // ------------------- PRODUCER WARPS (1..7) — identical to R7 -------
        const bool act = (lane < NLUT);
        const int  nl  = act ? lane : 0;

        // warp1 -> rows 0..5, warps 2..7 -> 20 rows each (6..125),
        // warp1 pass 2 -> rows 126..129 + 2 pads.
        const int s0 = (wrp == 1) ? 0 : 6 + 20 * (wrp - 2);
        const int nrows = (wrp == 1) ? 6 : 20;

        // Front-batch noise loads (max MLP) BEFORE the weights load.
        float4 nbuf[20];
#pragma unroll
        for (int i = 0; i < 20; ++i)
            if (i < nrows) nbuf[i] = noise4[(s0 + i) * NLUT + nl];

        float4 wb = make_float4(0.f, 0.f, 0.f, 0.f);
        if (act) wb = reinterpret_cast<const float4*>(weights)[lane];
        const float c0 = fabsf(1.0f - fabsf(wb.x)) * 0.125f;
        const float c1 = fabsf(1.0f - fabsf(wb.y)) * 0.125f;
        const float c2 = fabsf(1.0f - fabsf(wb.z)) * 0.125f;
        const float c3 = fabsf(1.0f - fabsf(wb.w)) * 0.125f;
        const float xv = (lane == 27) ? x[0] : ((lane == 28) ? x[1] : 0.0f);

#pragma unroll
        for (int i = 0; i < 20; ++i) {
            if (i >= nrows) break;
            const float4 n = nbuf[i];
            const float w0 = fmaf(c0, n.x, wb.x);
            const float w1 = fmaf(c1, n.y, wb.y);
            const float w2 = fmaf(c2, n.z, wb.z);
            const float w3 = fmaf(c3, n.w, wb.w);
            const float d01 = w1 - w0, d23 = w3 - w2;
            const float p01 = w0 + w1, p23 = w2 + w3;
            float4 q;
            q.x = act ? 0.25f * (d23 - d01) : 0.f;
            q.y = act ? 0.25f * (p23 - p01) : 0.f;
            q.z = act ? 0.25f * (d01 + d23) : 0.f;
            q.w = act ? 0.25f * (p01 + p23) : xv;
            s_uvrs[(s0 + i) * ROWS + lane] = q;
        }
        // warps 1..4: individual 64-thread barriers; warps 5..7 share bar 5.
        if (wrp <= 4) { int bw = wrp; BAR_ARRIVE(bw, 64); }
        else          { int b5 = 5;  BAR_ARRIVE(b5, 128); }

        if (wrp == 1) {
            // Second pass: rows 126..129 real, 130..131 zero padding.
            float4 nb2[4];
#pragma unroll
            for (int i = 0; i < 4; ++i)
                nb2[i] = noise4[(126 + i) * NLUT + nl];
#pragma unroll
            for (int i = 0; i < 4; ++i) {
                const float4 n = nb2[i];
                const float w0 = fmaf(c0, n.x, wb.x);
                const float w1 = fmaf(c1, n.y, wb.y);
                const float w2 = fmaf(c2, n.z, wb.z);
                const float w3 = fmaf(c3, n.w, wb.w);
                const float d01 = w1 - w0, d23 = w3 - w2;
                const float p01 = w0 + w1, p23 = w2 + w3;
                float4 q;
                q.x = act ? 0.25f * (d23 - d01) : 0.f;
                q.y = act ? 0.25f * (p23 - p01) : 0.f;
                q.z = act ? 0.25f * (d01 + d23) : 0.f;
                q.w = act ? 0.25f * (p01 + p23) : xv;
                s_uvrs[(126 + i) * ROWS + lane] = q;
            }
            s_uvrs[130 * ROWS + lane] = make_float4(0.f, 0.f, 0.f, 0.f);
            s_uvrs[131 * ROWS + lane] = make_float4(0.f, 0.f, 0.f, 0.f);
            int b8 = 8;
            BAR_ARRIVE(b8, 64);
        }
        return;
    }

    // ----------------------- CONSUMER WARP (0) -----------------------------
    // 1-step scan: minimum MIO ops per step (2 SHFL + 1 LDS.128).
    const int sa = c_srcA[lane];
    const int sb = c_srcB[lane];

    float state = (lane < NLUT) ? -1.0f
                : (lane == 27) ? x[0]
                : (lane == 28) ? x[1] : 0.0f;

    // Hoist step-0's shfls above the first barrier (depend only on init state).
    float A = __shfl_sync(0xFFFFFFFFu, state, sa);
    float B = __shfl_sync(0xFFFFFFFFu, state, sb);

    int b = 1;
    BAR_WAIT(b, 64);   // rows 0..5 ready

    const float4* pF = s_uvrs + lane;
    float4 q  = pF[0 * ROWS];   // row 0 (this step)
    float4 qn = pF[1 * ROWS];   // row 1 (next step)
    pF += 2 * ROWS;

    // Finish step 0.
    {
        const float4 qq = pF[0];  pF += ROWS;       // prefetch row 2
        state = fmaf(B, fmaf(A, q.x, q.y), fmaf(A, q.z, q.w));
        q = qn; qn = qq;
    }

// Per step: 2 SHFL (critical path) + 1 LDS.128 prefetch (2 rows ahead) + 3 FMA.
#define STEP1()                                                              \
    do {                                                                     \
        A = __shfl_sync(0xFFFFFFFFu, state, sa);                             \
        B = __shfl_sync(0xFFFFFFFFu, state, sb);                             \
        const float4 qq = pF[0];  pF += ROWS;                                \
        state = fmaf(B, fmaf(A, q.x, q.y), fmaf(A, q.z, q.w));               \
        q = qn; qn = qq;                                                     \
    } while (0)

    // Step s consumes row s, prefetches row s+2 (needs rows <= s+2):
    //   steps 0..3     rows <=5    (bar1, step 0 done above)
    //   steps 4..23    rows <=25   (bar2)   steps 24..43  rows <=45 (bar3)
    //   steps 44..63   rows <=65   (bar4)   steps 64..123 rows <=125 (bar5)
    //   steps 124..129 rows <=131  (bar8; pads cover over-read)
    STEP1(); STEP1(); STEP1();
    b = 2; BAR_WAIT(b, 64);
#pragma unroll
    for (int i = 0; i < 20; ++i) STEP1();
    b = 3; BAR_WAIT(b, 64);
#pragma unroll
    for (int i = 0; i < 20; ++i) STEP1();
    b = 4; BAR_WAIT(b, 64);
#pragma unroll
    for (int i = 0; i < 20; ++i) STEP1();
    b = 5; BAR_WAIT(b, 128);
#pragma unroll
    for (int i = 0; i < 60; ++i) STEP1();
    b = 8; BAR_WAIT(b, 64);
#pragma unroll
    for (int i = 0; i < 6; ++i) STEP1();

    // Outputs: final[0,1] -> flat 1, final[1,2] -> flat 5, final[7,2] -> flat 23.
    if (lane == 1)  out[0] = state;
    if (lane == 5)  out[1] = state;
    if (lane == 23) out[2] = state;
}

extern "C" void kernel_launch(void* const* d_in, const int* in_sizes, int n_in,
                              void* d_out, int out_size) {
    (void)in_sizes; (void)n_in; (void)out_size;
    const float*  x  = (const float*)d_in[0];      // [2]
    const float*  w  = (const float*)d_in[1];      // [9,3,4]
    const float4* nz = (const float4*)d_in[2];     // [130,9,3,4] as float4
    float* out = (float*)d_out;                    // [3]

    const size_t smem = (size_t)UROWS * ROWS * sizeof(float4);   // 67584 B
    cudaFuncSetAttribute(one_layer_net_kernel,
                         cudaFuncAttributeMaxDynamicSharedMemorySize, (int)smem);
    one_layer_net_kernel<<<1, 256, smem>>>(x, w, nz, out);
}